// round 16
// baseline (speedup 1.0000x reference)
#include <cuda_runtime.h>
#include <cuda_fp16.h>
#include <stdint.h>
#include <math.h>

#define NN 100000
#define EE 1600000
#define HH 4
#define DD 64
#define HD 256
#define NEG_SLOPE 0.2f
#define ROWCAP 64   // padded CSR row capacity (deg ~ Poisson(16); P(>64) ~ 1e-18)
#define GEMM_BX ((NN + 63) / 64)

// ---------------- scratch (device globals; referenced ONLY in device code) ----------------
__device__ __half   g_node_h[(size_t)NN * 128];
__device__ __half   g_Wh    [512 * 128];         // [W_fc | W_res_gat] transposed: [n][k]
__device__ __half   g_Wres_h[64 * 128];
__device__ __half   g_feat_h[(size_t)NN * HD];
__device__ __half   g_rst_h [(size_t)NN * HD];
__device__ float    g_el  [NN * HH];
__device__ float    g_er  [NN * HH];
__device__ float    g_h0  [NN * DD];
__device__ float    g_h   [NN * DD];
__device__ __half   g_xh  [(size_t)NN * DD];
__device__ __half   g_xh2 [(size_t)NN * DD];
__device__ float    g_norm[NN];
__device__ float    g_sum [DD];
__device__ float    g_sum2[DD];
__device__ float    g_mu  [DD];
__device__ float    g_rstd[DD];
// padded CSR
__device__ int      g_cur [NN];
__device__ int      g_csrc[(size_t)NN * ROWCAP + 4096];

// ---------------- converts + zeroing + cursor init (one kernel) ----------------
__global__ __launch_bounds__(256) void cvt_k(
    const float* __restrict__ node,
    const float* __restrict__ W_fc, const float* __restrict__ W_rg,
    const float* __restrict__ W_res)
{
    int i = blockIdx.x * blockDim.x + threadIdx.x;
    if (i < NN * 16) {   // 8 halves per thread
        const float4* src = reinterpret_cast<const float4*>(node);
        float4 x = src[i * 2], y = src[i * 2 + 1];
        __half2* dst = reinterpret_cast<__half2*>(&g_node_h[(size_t)i * 8]);
        dst[0] = __floats2half2_rn(x.x, x.y);
        dst[1] = __floats2half2_rn(x.z, x.w);
        dst[2] = __floats2half2_rn(y.x, y.y);
        dst[3] = __floats2half2_rn(y.z, y.w);
    }
    if (i < NN * 4) { g_el[i] = 0.f; g_er[i] = 0.f; }
    if (i < NN) g_cur[i] = i * ROWCAP;
    if (i < 512 * 128) {
        int n = i >> 7, k = i & 127;
        float v = (n < 256) ? W_fc[k * 256 + n] : W_rg[k * 256 + (n - 256)];
        g_Wh[i] = __float2half(v);
    }
    if (i < 64 * 128) g_Wres_h[i] = __float2half(W_res[i]);
    if (i < DD) { g_sum[i] = 0.f; g_sum2[i] = 0.f; }
}

// ---------------- fused fp16 mma GEMM + (y==4) padded-CSR scatter ----------------
__global__ __launch_bounds__(256) void gemm_mma_k(
    const float* __restrict__ attn_l, const float* __restrict__ attn_r,
    const float* __restrict__ bias,
    const int* __restrict__ src, const int* __restrict__ dst)
{
    const int nb = blockIdx.y;
    if (nb == 4) {
        int t = blockIdx.x * 256 + threadIdx.x;
        for (int e = t; e < EE; e += GEMM_BX * 256) {
            int slot = atomicAdd(&g_cur[dst[e]], 1);
            g_csrc[slot] = src[e];
        }
        return;
    }

    __shared__ unsigned int As2[64 * 36];
    __shared__ unsigned int Bs2[128 * 36];
    const int tid  = threadIdx.x;
    const int warp = tid >> 5, lane = tid & 31;
    const int gid  = lane >> 2, tig = lane & 3;
    const int wm   = warp >> 2, wn  = warp & 3;
    const int row0 = blockIdx.x * 64;
    const int nb0  = nb * 128;
    float c[2][4][4] = {};

    for (int kc = 0; kc < 128; kc += 64) {
#pragma unroll
        for (int it = 0; it < 2; it++) {
            int u = tid + it * 256;
            int r = u >> 3, q = u & 7;
            int grow = row0 + r;
            uint4 v = (grow < NN)
                ? *reinterpret_cast<const uint4*>(&g_node_h[(size_t)grow * 128 + kc + q * 8])
                : make_uint4(0u, 0u, 0u, 0u);
            *reinterpret_cast<uint4*>(&As2[r * 36 + q * 4]) = v;
        }
#pragma unroll
        for (int it = 0; it < 4; it++) {
            int u = tid + it * 256;
            int r = u >> 3, q = u & 7;
            uint4 v = *reinterpret_cast<const uint4*>(&g_Wh[(size_t)(nb0 + r) * 128 + kc + q * 8]);
            *reinterpret_cast<uint4*>(&Bs2[r * 36 + q * 4]) = v;
        }
        __syncthreads();
#pragma unroll
        for (int ks = 0; ks < 4; ks++) {
            int kb = ks * 8;
            unsigned int a[2][4], b[4][2];
#pragma unroll
            for (int mt = 0; mt < 2; mt++) {
                int rb = (wm * 32 + mt * 16 + gid) * 36 + kb + tig;
                a[mt][0] = As2[rb];
                a[mt][1] = As2[rb + 8 * 36];
                a[mt][2] = As2[rb + 4];
                a[mt][3] = As2[rb + 8 * 36 + 4];
            }
#pragma unroll
            for (int nt = 0; nt < 4; nt++) {
                int nbase = (wn * 32 + nt * 8 + gid) * 36 + kb + tig;
                b[nt][0] = Bs2[nbase];
                b[nt][1] = Bs2[nbase + 4];
            }
#pragma unroll
            for (int mt = 0; mt < 2; mt++)
#pragma unroll
                for (int nt = 0; nt < 4; nt++)
                    asm volatile(
                        "mma.sync.aligned.m16n8k16.row.col.f32.f16.f16.f32 "
                        "{%0,%1,%2,%3}, {%4,%5,%6,%7}, {%8,%9}, {%0,%1,%2,%3};"
                        : "+f"(c[mt][nt][0]), "+f"(c[mt][nt][1]),
                          "+f"(c[mt][nt][2]), "+f"(c[mt][nt][3])
                        : "r"(a[mt][0]), "r"(a[mt][1]), "r"(a[mt][2]), "r"(a[mt][3]),
                          "r"(b[nt][0]), "r"(b[nt][1]));
        }
        __syncthreads();
    }

    if (nb < 2) {
        float pel[2][2] = {}, per_[2][2] = {};
#pragma unroll
        for (int nt = 0; nt < 4; nt++) {
            int gc = nb * 128 + wn * 32 + nt * 8 + tig * 2;
            float al0 = attn_l[gc], al1 = attn_l[gc + 1];
            float ar0 = attn_r[gc], ar1 = attn_r[gc + 1];
#pragma unroll
            for (int mt = 0; mt < 2; mt++) {
                int rlo = row0 + wm * 32 + mt * 16 + gid;
                if (rlo < NN)
                    *reinterpret_cast<__half2*>(&g_feat_h[(size_t)rlo * 256 + gc]) =
                        __floats2half2_rn(c[mt][nt][0], c[mt][nt][1]);
                if (rlo + 8 < NN)
                    *reinterpret_cast<__half2*>(&g_feat_h[(size_t)(rlo + 8) * 256 + gc]) =
                        __floats2half2_rn(c[mt][nt][2], c[mt][nt][3]);
                pel[mt][0]  += c[mt][nt][0] * al0 + c[mt][nt][1] * al1;
                pel[mt][1]  += c[mt][nt][2] * al0 + c[mt][nt][3] * al1;
                per_[mt][0] += c[mt][nt][0] * ar0 + c[mt][nt][1] * ar1;
                per_[mt][1] += c[mt][nt][2] * ar0 + c[mt][nt][3] * ar1;
            }
        }
#pragma unroll
        for (int mt = 0; mt < 2; mt++)
#pragma unroll
            for (int rh = 0; rh < 2; rh++) {
                float e = pel[mt][rh], f = per_[mt][rh];
                e += __shfl_xor_sync(0xFFFFFFFFu, e, 1);
                e += __shfl_xor_sync(0xFFFFFFFFu, e, 2);
                f += __shfl_xor_sync(0xFFFFFFFFu, f, 1);
                f += __shfl_xor_sync(0xFFFFFFFFu, f, 2);
                if (tig == 0) {
                    int r = row0 + wm * 32 + mt * 16 + gid + rh * 8;
                    int h = (nb * 128 + wn * 32) >> 6;
                    if (r < NN) {
                        atomicAdd(&g_el[r * 4 + h], e);
                        atomicAdd(&g_er[r * 4 + h], f);
                    }
                }
            }
    } else {
#pragma unroll
        for (int nt = 0; nt < 4; nt++) {
            int gc = (nb - 2) * 128 + wn * 32 + nt * 8 + tig * 2;
            float b0 = bias[gc], b1 = bias[gc + 1];
#pragma unroll
            for (int mt = 0; mt < 2; mt++) {
                int rlo = row0 + wm * 32 + mt * 16 + gid;
                if (rlo < NN)
                    *reinterpret_cast<__half2*>(&g_rst_h[(size_t)rlo * 256 + gc]) =
                        __floats2half2_rn(c[mt][nt][0] + b0, c[mt][nt][1] + b1);
                if (rlo + 8 < NN)
                    *reinterpret_cast<__half2*>(&g_rst_h[(size_t)(rlo + 8) * 256 + gc]) =
                        __floats2half2_rn(c[mt][nt][2] + b0, c[mt][nt][3] + b1);
            }
        }
    }
}

// ---------------- residual mma GEMM: h = g_h + relu(node @ W_res^T + b) ; fused BN stats ----------------
__global__ __launch_bounds__(128) void gemm_res_k(const float* __restrict__ bias) {
    __shared__ unsigned int As2[64 * 36];
    __shared__ unsigned int Bs2[64 * 36];
    const int tid  = threadIdx.x;
    const int warp = tid >> 5, lane = tid & 31;
    const int gid  = lane >> 2, tig = lane & 3;
    const int wm   = warp >> 1, wn  = warp & 1;
    const int row0 = blockIdx.x * 64;
    float c[2][4][4] = {};

    for (int kc = 0; kc < 128; kc += 64) {
#pragma unroll
        for (int it = 0; it < 4; it++) {
            int u = tid + it * 128;
            int r = u >> 3, q = u & 7;
            int grow = row0 + r;
            uint4 v = (grow < NN)
                ? *reinterpret_cast<const uint4*>(&g_node_h[(size_t)grow * 128 + kc + q * 8])
                : make_uint4(0u, 0u, 0u, 0u);
            *reinterpret_cast<uint4*>(&As2[r * 36 + q * 4]) = v;
        }
#pragma unroll
        for (int it = 0; it < 4; it++) {
            int u = tid + it * 128;
            int r = u >> 3, q = u & 7;
            uint4 v = *reinterpret_cast<const uint4*>(&g_Wres_h[(size_t)r * 128 + kc + q * 8]);
            *reinterpret_cast<uint4*>(&Bs2[r * 36 + q * 4]) = v;
        }
        __syncthreads();
#pragma unroll
        for (int ks = 0; ks < 4; ks++) {
            int kb = ks * 8;
            unsigned int a[2][4], b[4][2];
#pragma unroll
            for (int mt = 0; mt < 2; mt++) {
                int rb = (wm * 32 + mt * 16 + gid) * 36 + kb + tig;
                a[mt][0] = As2[rb];
                a[mt][1] = As2[rb + 8 * 36];
                a[mt][2] = As2[rb + 4];
                a[mt][3] = As2[rb + 8 * 36 + 4];
            }
#pragma unroll
            for (int nt = 0; nt < 4; nt++) {
                int nbase = (wn * 32 + nt * 8 + gid) * 36 + kb + tig;
                b[nt][0] = Bs2[nbase];
                b[nt][1] = Bs2[nbase + 4];
            }
#pragma unroll
            for (int mt = 0; mt < 2; mt++)
#pragma unroll
                for (int nt = 0; nt < 4; nt++)
                    asm volatile(
                        "mma.sync.aligned.m16n8k16.row.col.f32.f16.f16.f32 "
                        "{%0,%1,%2,%3}, {%4,%5,%6,%7}, {%8,%9}, {%0,%1,%2,%3};"
                        : "+f"(c[mt][nt][0]), "+f"(c[mt][nt][1]),
                          "+f"(c[mt][nt][2]), "+f"(c[mt][nt][3])
                        : "r"(a[mt][0]), "r"(a[mt][1]), "r"(a[mt][2]), "r"(a[mt][3]),
                          "r"(b[nt][0]), "r"(b[nt][1]));
        }
        __syncthreads();
    }
#pragma unroll
    for (int nt = 0; nt < 4; nt++) {
        int gc = wn * 32 + nt * 8 + tig * 2;
        float b0 = bias[gc], b1 = bias[gc + 1];
        float s0 = 0.f, s1 = 0.f, q0 = 0.f, q1 = 0.f;
#pragma unroll
        for (int mt = 0; mt < 2; mt++) {
            int rlo = row0 + wm * 32 + mt * 16 + gid;
            if (rlo < NN) {
                float h0 = g_h[(size_t)rlo * 64 + gc]     + fmaxf(c[mt][nt][0] + b0, 0.f);
                float h1 = g_h[(size_t)rlo * 64 + gc + 1] + fmaxf(c[mt][nt][1] + b1, 0.f);
                g_h[(size_t)rlo * 64 + gc]     = h0;
                g_h[(size_t)rlo * 64 + gc + 1] = h1;
                s0 += h0; q0 += h0 * h0;
                s1 += h1; q1 += h1 * h1;
            }
            if (rlo + 8 < NN) {
                float h0 = g_h[(size_t)(rlo + 8) * 64 + gc]     + fmaxf(c[mt][nt][2] + b0, 0.f);
                float h1 = g_h[(size_t)(rlo + 8) * 64 + gc + 1] + fmaxf(c[mt][nt][3] + b1, 0.f);
                g_h[(size_t)(rlo + 8) * 64 + gc]     = h0;
                g_h[(size_t)(rlo + 8) * 64 + gc + 1] = h1;
                s0 += h0; q0 += h0 * h0;
                s1 += h1; q1 += h1 * h1;
            }
        }
#pragma unroll
        for (int o = 4; o < 32; o <<= 1) {
            s0 += __shfl_xor_sync(0xFFFFFFFFu, s0, o);
            s1 += __shfl_xor_sync(0xFFFFFFFFu, s1, o);
            q0 += __shfl_xor_sync(0xFFFFFFFFu, q0, o);
            q1 += __shfl_xor_sync(0xFFFFFFFFu, q1, o);
        }
        if (gid == 0) {
            atomicAdd(&g_sum[gc],      s0);
            atomicAdd(&g_sum[gc + 1],  s1);
            atomicAdd(&g_sum2[gc],     q0);
            atomicAdd(&g_sum2[gc + 1], q1);
        }
    }
}

// ---------------- fused softmax + GAT aggregate + conv + APPNP init: warp per node ----------------
__global__ __launch_bounds__(256) void msg_fused_k(
    const float* __restrict__ conv_w, const float* __restrict__ conv_b)
{
    int w = (blockIdx.x * blockDim.x + threadIdx.x) >> 5;
    int lane = threadIdx.x & 31;
    if (w >= NN) return;
    int r0 = w * ROWCAP, r1 = g_cur[w];
    const int hl = lane >> 3;
    const float er_s = g_er[w * 4 + hl];
    const uint4* __restrict__ fh4 = reinterpret_cast<const uint4*>(g_feat_h);
    unsigned long long accp[4] = {0ull, 0ull, 0ull, 0ull};
    float dsum = 0.f;

    for (int base = r0; base < r1; base += 32) {
        int nb = min(32, r1 - base);
        int idx = (base + lane < r1) ? g_csrc[base + lane] : 0;
        int j = 0;
        for (; j + 1 < nb; j += 2) {
            int s0 = __shfl_sync(0xFFFFFFFFu, idx, j);
            int s1 = __shfl_sync(0xFFFFFFFFu, idx, j + 1);
            float x0 = g_el[s0 * 4 + hl] + er_s;
            float x1 = g_el[s1 * 4 + hl] + er_s;
            uint4 f0 = fh4[(size_t)s0 * 32 + lane];
            uint4 f1 = fh4[(size_t)s1 * 32 + lane];
            x0 = (x0 > 0.f) ? x0 : NEG_SLOPE * x0;
            x1 = (x1 > 0.f) ? x1 : NEG_SLOPE * x1;
            float w0 = __expf(x0), w1 = __expf(x1);
            dsum += w0 + w1;
            unsigned long long wp0, wp1;
            asm("mov.b64 %0, {%1, %1};" : "=l"(wp0) : "f"(w0));
            asm("mov.b64 %0, {%1, %1};" : "=l"(wp1) : "f"(w1));
            const __half2* p0 = reinterpret_cast<const __half2*>(&f0);
            const __half2* p1 = reinterpret_cast<const __half2*>(&f1);
#pragma unroll
            for (int i = 0; i < 4; i++) {
                float2 t0 = __half22float2(p0[i]);
                float2 t1 = __half22float2(p1[i]);
                unsigned long long tp0, tp1;
                asm("mov.b64 %0, {%1, %2};" : "=l"(tp0) : "f"(t0.x), "f"(t0.y));
                asm("mov.b64 %0, {%1, %2};" : "=l"(tp1) : "f"(t1.x), "f"(t1.y));
                asm("fma.rn.f32x2 %0, %1, %2, %0;" : "+l"(accp[i]) : "l"(wp0), "l"(tp0));
                asm("fma.rn.f32x2 %0, %1, %2, %0;" : "+l"(accp[i]) : "l"(wp1), "l"(tp1));
            }
        }
        if (j < nb) {
            int s0 = __shfl_sync(0xFFFFFFFFu, idx, j);
            float x0 = g_el[s0 * 4 + hl] + er_s;
            uint4 f0 = fh4[(size_t)s0 * 32 + lane];
            x0 = (x0 > 0.f) ? x0 : NEG_SLOPE * x0;
            float w0 = __expf(x0);
            dsum += w0;
            unsigned long long wp0;
            asm("mov.b64 %0, {%1, %1};" : "=l"(wp0) : "f"(w0));
            const __half2* p0 = reinterpret_cast<const __half2*>(&f0);
#pragma unroll
            for (int i = 0; i < 4; i++) {
                float2 t0 = __half22float2(p0[i]);
                unsigned long long tp0;
                asm("mov.b64 %0, {%1, %2};" : "=l"(tp0) : "f"(t0.x), "f"(t0.y));
                asm("fma.rn.f32x2 %0, %1, %2, %0;" : "+l"(accp[i]) : "l"(wp0), "l"(tp0));
            }
        }
    }

    float acc[8];
#pragma unroll
    for (int i = 0; i < 4; i++)
        asm("mov.b64 {%0, %1}, %2;" : "=f"(acc[2*i]), "=f"(acc[2*i+1]) : "l"(accp[i]));

    float rden = 1.f / fmaxf(dsum, 1e-9f);
    uint4 rvu = reinterpret_cast<const uint4*>(g_rst_h)[(size_t)w * 32 + lane];
    const __half2* rp = reinterpret_cast<const __half2*>(&rvu);
    float cwh = conv_w[hl];
    float v[8];
#pragma unroll
    for (int i = 0; i < 4; i++) {
        float2 rv = __half22float2(rp[i]);
        v[2*i]   = fmaxf(acc[2*i]   * rden + rv.x, 0.f) * cwh;
        v[2*i+1] = fmaxf(acc[2*i+1] * rden + rv.y, 0.f) * cwh;
    }
#pragma unroll
    for (int i = 0; i < 8; i++) {
        v[i] += __shfl_xor_sync(0xFFFFFFFFu, v[i], 8);
        v[i] += __shfl_xor_sync(0xFFFFFFFFu, v[i], 16);
    }
    float cb = conv_b[0];
#pragma unroll
    for (int i = 0; i < 8; i++) v[i] += cb;
    float nm = rsqrtf(fmaxf((float)(r1 - r0), 1.f));
    int q = lane & 7;
    if (lane == 0) g_norm[w] = nm;
    if (lane < 8) {
        float4 a = make_float4(v[0], v[1], v[2], v[3]);
        float4 b = make_float4(v[4], v[5], v[6], v[7]);
        reinterpret_cast<float4*>(g_h0)[(size_t)w * 16 + q * 2]     = a;
        reinterpret_cast<float4*>(g_h0)[(size_t)w * 16 + q * 2 + 1] = b;
    } else if (lane < 16) {
        __half2 hx[4];
#pragma unroll
        for (int i = 0; i < 4; i++)
            hx[i] = __floats2half2_rn(v[2*i] * nm, v[2*i+1] * nm);
        reinterpret_cast<uint4*>(g_xh)[(size_t)w * 8 + q] =
            *reinterpret_cast<uint4*>(hx);
    }
}

// ---------------- fused APPNP propagate+combine: warp per node, quarter-warp per edge ----------------
// uint4 gathers (1 LDG per edge per lane-slice); HADD2 fp16 accumulation, fp32 flush every 16 edges.
__global__ __launch_bounds__(256) void prop_k(int it) {
    int w = (blockIdx.x * blockDim.x + threadIdx.x) >> 5;
    int lane = threadIdx.x & 31;
    if (w >= NN) return;
    const int qid = lane >> 3, sub = lane & 7;
    const uint4* __restrict__ xin4 =
        reinterpret_cast<const uint4*>((it & 1) ? g_xh2 : g_xh);   // row = 8 uint4
    int r0 = w * ROWCAP, r1 = g_cur[w];
    float fa[8] = {};

    for (int base = r0; base < r1; base += 32) {
        int nb = min(32, r1 - base);
        int idx = (base + lane < r1) ? g_csrc[base + lane] : 0;
#pragma unroll
        for (int run = 0; run < 2; run++) {       // two 16-edge runs per chunk
            int j0 = run * 16;
            if (j0 >= nb) break;
            int jend = min(j0 + 16, nb);
            __half2 hacc0 = __float2half2_rn(0.f), hacc1 = hacc0;
            __half2 hacc2 = hacc0, hacc3 = hacc0;
            for (int j = j0; j < jend; j += 4) {
                int e = j + qid;
                int s = __shfl_sync(0xFFFFFFFFu, idx, e);
                if (e < jend) {
                    uint4 u = xin4[(size_t)s * 8 + sub];
                    const __half2* p = reinterpret_cast<const __half2*>(&u);
                    hacc0 = __hadd2(hacc0, p[0]);
                    hacc1 = __hadd2(hacc1, p[1]);
                    hacc2 = __hadd2(hacc2, p[2]);
                    hacc3 = __hadd2(hacc3, p[3]);
                }
            }
            float2 t0 = __half22float2(hacc0);
            float2 t1 = __half22float2(hacc1);
            float2 t2 = __half22float2(hacc2);
            float2 t3 = __half22float2(hacc3);
            fa[0] += t0.x; fa[1] += t0.y;
            fa[2] += t1.x; fa[3] += t1.y;
            fa[4] += t2.x; fa[5] += t2.y;
            fa[6] += t3.x; fa[7] += t3.y;
        }
    }
    // reduce across the 4 quarter-warps (same columns in each)
#pragma unroll
    for (int i = 0; i < 8; i++) {
        fa[i] += __shfl_xor_sync(0xFFFFFFFFu, fa[i], 8);
        fa[i] += __shfl_xor_sync(0xFFFFFFFFu, fa[i], 16);
    }

    if (qid == 0) {   // lanes 0..7, lane sub owns columns sub*8 .. sub*8+7
        float nm = g_norm[w];
        float4 h0a = reinterpret_cast<const float4*>(g_h0)[(size_t)w * 16 + sub * 2];
        float4 h0b = reinterpret_cast<const float4*>(g_h0)[(size_t)w * 16 + sub * 2 + 1];
        float t[8];
        t[0] = 0.5f * fa[0] * nm + 0.5f * h0a.x;
        t[1] = 0.5f * fa[1] * nm + 0.5f * h0a.y;
        t[2] = 0.5f * fa[2] * nm + 0.5f * h0a.z;
        t[3] = 0.5f * fa[3] * nm + 0.5f * h0a.w;
        t[4] = 0.5f * fa[4] * nm + 0.5f * h0b.x;
        t[5] = 0.5f * fa[5] * nm + 0.5f * h0b.y;
        t[6] = 0.5f * fa[6] * nm + 0.5f * h0b.z;
        t[7] = 0.5f * fa[7] * nm + 0.5f * h0b.w;
        if (it == 4) {
            reinterpret_cast<float4*>(g_h)[(size_t)w * 16 + sub * 2] =
                make_float4(t[0], t[1], t[2], t[3]);
            reinterpret_cast<float4*>(g_h)[(size_t)w * 16 + sub * 2 + 1] =
                make_float4(t[4], t[5], t[6], t[7]);
        } else {
            __half2 hx[4];
#pragma unroll
            for (int i = 0; i < 4; i++)
                hx[i] = __floats2half2_rn(t[2*i] * nm, t[2*i+1] * nm);
            uint4* xout = reinterpret_cast<uint4*>((it & 1) ? g_xh : g_xh2);
            xout[(size_t)w * 8 + sub] = *reinterpret_cast<uint4*>(hx);
        }
    }
}

// ---------------- BatchNorm finalize + output ----------------
__global__ void bnfin_k() {
    int c = threadIdx.x;
    if (c >= DD) return;
    double mu = (double)g_sum[c] / NN;
    double var = (double)g_sum2[c] / NN - mu * mu;
    g_mu[c]   = (float)mu;
    g_rstd[c] = (float)(1.0 / sqrt(var + 1e-5));
}

__global__ __launch_bounds__(256) void bnout_k(
    const float* __restrict__ gamma, const float* __restrict__ beta,
    float* __restrict__ out)
{
    int i = blockIdx.x * blockDim.x + threadIdx.x;
    if (i >= NN * DD) return;
    int c = i & 63;
    out[i] = (g_h[i] - g_mu[c]) * g_rstd[c] * gamma[c] + beta[c];
}

// ---------------- launch ----------------
extern "C" void kernel_launch(void* const* d_in, const int* in_sizes, int n_in,
                              void* d_out, int out_size) {
    const float* node      = (const float*)d_in[0];
    const int*   src       = (const int*)  d_in[1];
    const int*   dst       = (const int*)  d_in[2];
    const float* W_fc      = (const float*)d_in[3];
    const float* attn_l    = (const float*)d_in[4];
    const float* attn_r    = (const float*)d_in[5];
    const float* W_res_gat = (const float*)d_in[6];
    const float* gat_bias  = (const float*)d_in[7];
    const float* conv_w    = (const float*)d_in[8];
    const float* conv_b    = (const float*)d_in[9];
    const float* W_res     = (const float*)d_in[10];
    const float* b_res     = (const float*)d_in[11];
    const float* gamma     = (const float*)d_in[12];
    const float* beta      = (const float*)d_in[13];
    float* out = (float*)d_out;

    cvt_k<<<(NN*16 + 255)/256, 256>>>(node, W_fc, W_res_gat, W_res);

    dim3 gg(GEMM_BX, 5);
    gemm_mma_k<<<gg, 256>>>(attn_l, attn_r, gat_bias, src, dst);

    msg_fused_k<<<(NN*32 + 255)/256, 256>>>(conv_w, conv_b);

    for (int it = 0; it < 5; it++)
        prop_k<<<(NN*32 + 255)/256, 256>>>(it);

    gemm_res_k<<<(NN + 63)/64, 128>>>(b_res);

    bnfin_k<<<1, 64>>>();
    bnout_k<<<(NN*DD + 255)/256, 256>>>(gamma, beta, out);
}

// round 17
// speedup vs baseline: 1.0119x; 1.0119x over previous
#include <cuda_runtime.h>
#include <cuda_fp16.h>
#include <stdint.h>
#include <math.h>

#define NN 100000
#define EE 1600000
#define HH 4
#define DD 64
#define HD 256
#define NEG_SLOPE 0.2f
#define ROWCAP 64   // padded CSR row capacity (deg ~ Poisson(16); P(>64) ~ 1e-18)
#define GEMM_BX ((NN + 63) / 64)

// ---------------- scratch (device globals; referenced ONLY in device code) ----------------
__device__ __half   g_node_h[(size_t)NN * 128];
__device__ __half   g_Wh    [512 * 128];         // [W_fc | W_res_gat] transposed: [n][k]
__device__ __half   g_Wres_h[64 * 128];
__device__ __half   g_feat_h[(size_t)NN * HD];
__device__ __half   g_rst_h [(size_t)NN * HD];
__device__ float    g_el  [NN * HH];
__device__ float    g_er  [NN * HH];
__device__ float    g_h0  [NN * DD];
__device__ float    g_h   [NN * DD];
__device__ __half   g_xh  [(size_t)NN * DD];
__device__ __half   g_xh2 [(size_t)NN * DD];
__device__ float    g_norm[NN];
__device__ float    g_sum [DD];
__device__ float    g_sum2[DD];
__device__ float    g_mu  [DD];
__device__ float    g_rstd[DD];
// padded CSR
__device__ int      g_cur [NN];
__device__ int      g_csrc[(size_t)NN * ROWCAP + 4096];

// ---------------- converts + zeroing + cursor init (one kernel) ----------------
__global__ __launch_bounds__(256) void cvt_k(
    const float* __restrict__ node,
    const float* __restrict__ W_fc, const float* __restrict__ W_rg,
    const float* __restrict__ W_res)
{
    int i = blockIdx.x * blockDim.x + threadIdx.x;
    if (i < NN * 16) {   // 8 halves per thread
        const float4* src = reinterpret_cast<const float4*>(node);
        float4 x = src[i * 2], y = src[i * 2 + 1];
        __half2* dst = reinterpret_cast<__half2*>(&g_node_h[(size_t)i * 8]);
        dst[0] = __floats2half2_rn(x.x, x.y);
        dst[1] = __floats2half2_rn(x.z, x.w);
        dst[2] = __floats2half2_rn(y.x, y.y);
        dst[3] = __floats2half2_rn(y.z, y.w);
    }
    if (i < NN * 4) { g_el[i] = 0.f; g_er[i] = 0.f; }
    if (i < NN) g_cur[i] = i * ROWCAP;
    if (i < 512 * 128) {
        int n = i >> 7, k = i & 127;
        float v = (n < 256) ? W_fc[k * 256 + n] : W_rg[k * 256 + (n - 256)];
        g_Wh[i] = __float2half(v);
    }
    if (i < 64 * 128) g_Wres_h[i] = __float2half(W_res[i]);
    if (i < DD) { g_sum[i] = 0.f; g_sum2[i] = 0.f; }
}

// ---------------- fused fp16 mma GEMM + (y==4) padded-CSR scatter ----------------
// ldmatrix fragment loads (A: x4, B: x2); 36-uint row stride is 8-row conflict-free.
__global__ __launch_bounds__(256) void gemm_mma_k(
    const float* __restrict__ attn_l, const float* __restrict__ attn_r,
    const float* __restrict__ bias,
    const int* __restrict__ src, const int* __restrict__ dst)
{
    const int nb = blockIdx.y;
    if (nb == 4) {
        int t = blockIdx.x * 256 + threadIdx.x;
        for (int e = t; e < EE; e += GEMM_BX * 256) {
            int slot = atomicAdd(&g_cur[dst[e]], 1);
            g_csrc[slot] = src[e];
        }
        return;
    }

    __shared__ unsigned int As2[64 * 36];
    __shared__ unsigned int Bs2[128 * 36];
    const int tid  = threadIdx.x;
    const int warp = tid >> 5, lane = tid & 31;
    const int gid  = lane >> 2, tig = lane & 3;
    const int wm   = warp >> 2, wn  = warp & 3;
    const int row0 = blockIdx.x * 64;
    const int nb0  = nb * 128;
    float c[2][4][4] = {};

    for (int kc = 0; kc < 128; kc += 64) {
#pragma unroll
        for (int it = 0; it < 2; it++) {
            int u = tid + it * 256;
            int r = u >> 3, q = u & 7;
            int grow = row0 + r;
            uint4 v = (grow < NN)
                ? *reinterpret_cast<const uint4*>(&g_node_h[(size_t)grow * 128 + kc + q * 8])
                : make_uint4(0u, 0u, 0u, 0u);
            *reinterpret_cast<uint4*>(&As2[r * 36 + q * 4]) = v;
        }
#pragma unroll
        for (int it = 0; it < 4; it++) {
            int u = tid + it * 256;
            int r = u >> 3, q = u & 7;
            uint4 v = *reinterpret_cast<const uint4*>(&g_Wh[(size_t)(nb0 + r) * 128 + kc + q * 8]);
            *reinterpret_cast<uint4*>(&Bs2[r * 36 + q * 4]) = v;
        }
        __syncthreads();
#pragma unroll
        for (int ks = 0; ks < 4; ks++) {
            int kb = ks * 8;
            unsigned int a[2][4], b[4][2];
#pragma unroll
            for (int mt = 0; mt < 2; mt++) {
                const unsigned int* pa =
                    &As2[(wm * 32 + mt * 16 + (lane & 15)) * 36 + kb + ((lane >> 4) << 2)];
                unsigned int sa = (unsigned int)__cvta_generic_to_shared(pa);
                asm volatile(
                    "ldmatrix.sync.aligned.m8n8.x4.shared.b16 {%0,%1,%2,%3}, [%4];"
                    : "=r"(a[mt][0]), "=r"(a[mt][1]), "=r"(a[mt][2]), "=r"(a[mt][3])
                    : "r"(sa));
            }
#pragma unroll
            for (int nt = 0; nt < 4; nt++) {
                const unsigned int* pb =
                    &Bs2[(wn * 32 + nt * 8 + (lane & 7)) * 36 + kb + (((lane >> 3) & 1) << 2)];
                unsigned int sb = (unsigned int)__cvta_generic_to_shared(pb);
                asm volatile(
                    "ldmatrix.sync.aligned.m8n8.x2.shared.b16 {%0,%1}, [%2];"
                    : "=r"(b[nt][0]), "=r"(b[nt][1])
                    : "r"(sb));
            }
#pragma unroll
            for (int mt = 0; mt < 2; mt++)
#pragma unroll
                for (int nt = 0; nt < 4; nt++)
                    asm volatile(
                        "mma.sync.aligned.m16n8k16.row.col.f32.f16.f16.f32 "
                        "{%0,%1,%2,%3}, {%4,%5,%6,%7}, {%8,%9}, {%0,%1,%2,%3};"
                        : "+f"(c[mt][nt][0]), "+f"(c[mt][nt][1]),
                          "+f"(c[mt][nt][2]), "+f"(c[mt][nt][3])
                        : "r"(a[mt][0]), "r"(a[mt][1]), "r"(a[mt][2]), "r"(a[mt][3]),
                          "r"(b[nt][0]), "r"(b[nt][1]));
        }
        __syncthreads();
    }

    if (nb < 2) {
        float pel[2][2] = {}, per_[2][2] = {};
#pragma unroll
        for (int nt = 0; nt < 4; nt++) {
            int gc = nb * 128 + wn * 32 + nt * 8 + tig * 2;
            float al0 = attn_l[gc], al1 = attn_l[gc + 1];
            float ar0 = attn_r[gc], ar1 = attn_r[gc + 1];
#pragma unroll
            for (int mt = 0; mt < 2; mt++) {
                int rlo = row0 + wm * 32 + mt * 16 + gid;
                if (rlo < NN)
                    *reinterpret_cast<__half2*>(&g_feat_h[(size_t)rlo * 256 + gc]) =
                        __floats2half2_rn(c[mt][nt][0], c[mt][nt][1]);
                if (rlo + 8 < NN)
                    *reinterpret_cast<__half2*>(&g_feat_h[(size_t)(rlo + 8) * 256 + gc]) =
                        __floats2half2_rn(c[mt][nt][2], c[mt][nt][3]);
                pel[mt][0]  += c[mt][nt][0] * al0 + c[mt][nt][1] * al1;
                pel[mt][1]  += c[mt][nt][2] * al0 + c[mt][nt][3] * al1;
                per_[mt][0] += c[mt][nt][0] * ar0 + c[mt][nt][1] * ar1;
                per_[mt][1] += c[mt][nt][2] * ar0 + c[mt][nt][3] * ar1;
            }
        }
#pragma unroll
        for (int mt = 0; mt < 2; mt++)
#pragma unroll
            for (int rh = 0; rh < 2; rh++) {
                float e = pel[mt][rh], f = per_[mt][rh];
                e += __shfl_xor_sync(0xFFFFFFFFu, e, 1);
                e += __shfl_xor_sync(0xFFFFFFFFu, e, 2);
                f += __shfl_xor_sync(0xFFFFFFFFu, f, 1);
                f += __shfl_xor_sync(0xFFFFFFFFu, f, 2);
                if (tig == 0) {
                    int r = row0 + wm * 32 + mt * 16 + gid + rh * 8;
                    int h = (nb * 128 + wn * 32) >> 6;
                    if (r < NN) {
                        atomicAdd(&g_el[r * 4 + h], e);
                        atomicAdd(&g_er[r * 4 + h], f);
                    }
                }
            }
    } else {
#pragma unroll
        for (int nt = 0; nt < 4; nt++) {
            int gc = (nb - 2) * 128 + wn * 32 + nt * 8 + tig * 2;
            float b0 = bias[gc], b1 = bias[gc + 1];
#pragma unroll
            for (int mt = 0; mt < 2; mt++) {
                int rlo = row0 + wm * 32 + mt * 16 + gid;
                if (rlo < NN)
                    *reinterpret_cast<__half2*>(&g_rst_h[(size_t)rlo * 256 + gc]) =
                        __floats2half2_rn(c[mt][nt][0] + b0, c[mt][nt][1] + b1);
                if (rlo + 8 < NN)
                    *reinterpret_cast<__half2*>(&g_rst_h[(size_t)(rlo + 8) * 256 + gc]) =
                        __floats2half2_rn(c[mt][nt][2] + b0, c[mt][nt][3] + b1);
            }
        }
    }
}

// ---------------- residual mma GEMM: h = g_h + relu(node @ W_res^T + b) ; fused BN stats ----------------
__global__ __launch_bounds__(128) void gemm_res_k(const float* __restrict__ bias) {
    __shared__ unsigned int As2[64 * 36];
    __shared__ unsigned int Bs2[64 * 36];
    const int tid  = threadIdx.x;
    const int warp = tid >> 5, lane = tid & 31;
    const int gid  = lane >> 2, tig = lane & 3;
    const int wm   = warp >> 1, wn  = warp & 1;
    const int row0 = blockIdx.x * 64;
    float c[2][4][4] = {};

    for (int kc = 0; kc < 128; kc += 64) {
#pragma unroll
        for (int it = 0; it < 4; it++) {
            int u = tid + it * 128;
            int r = u >> 3, q = u & 7;
            int grow = row0 + r;
            uint4 v = (grow < NN)
                ? *reinterpret_cast<const uint4*>(&g_node_h[(size_t)grow * 128 + kc + q * 8])
                : make_uint4(0u, 0u, 0u, 0u);
            *reinterpret_cast<uint4*>(&As2[r * 36 + q * 4]) = v;
        }
#pragma unroll
        for (int it = 0; it < 4; it++) {
            int u = tid + it * 128;
            int r = u >> 3, q = u & 7;
            uint4 v = *reinterpret_cast<const uint4*>(&g_Wres_h[(size_t)r * 128 + kc + q * 8]);
            *reinterpret_cast<uint4*>(&Bs2[r * 36 + q * 4]) = v;
        }
        __syncthreads();
#pragma unroll
        for (int ks = 0; ks < 4; ks++) {
            int kb = ks * 8;
            unsigned int a[2][4], b[4][2];
#pragma unroll
            for (int mt = 0; mt < 2; mt++) {
                int rb = (wm * 32 + mt * 16 + gid) * 36 + kb + tig;
                a[mt][0] = As2[rb];
                a[mt][1] = As2[rb + 8 * 36];
                a[mt][2] = As2[rb + 4];
                a[mt][3] = As2[rb + 8 * 36 + 4];
            }
#pragma unroll
            for (int nt = 0; nt < 4; nt++) {
                int nbase = (wn * 32 + nt * 8 + gid) * 36 + kb + tig;
                b[nt][0] = Bs2[nbase];
                b[nt][1] = Bs2[nbase + 4];
            }
#pragma unroll
            for (int mt = 0; mt < 2; mt++)
#pragma unroll
                for (int nt = 0; nt < 4; nt++)
                    asm volatile(
                        "mma.sync.aligned.m16n8k16.row.col.f32.f16.f16.f32 "
                        "{%0,%1,%2,%3}, {%4,%5,%6,%7}, {%8,%9}, {%0,%1,%2,%3};"
                        : "+f"(c[mt][nt][0]), "+f"(c[mt][nt][1]),
                          "+f"(c[mt][nt][2]), "+f"(c[mt][nt][3])
                        : "r"(a[mt][0]), "r"(a[mt][1]), "r"(a[mt][2]), "r"(a[mt][3]),
                          "r"(b[nt][0]), "r"(b[nt][1]));
        }
        __syncthreads();
    }
#pragma unroll
    for (int nt = 0; nt < 4; nt++) {
        int gc = wn * 32 + nt * 8 + tig * 2;
        float b0 = bias[gc], b1 = bias[gc + 1];
        float s0 = 0.f, s1 = 0.f, q0 = 0.f, q1 = 0.f;
#pragma unroll
        for (int mt = 0; mt < 2; mt++) {
            int rlo = row0 + wm * 32 + mt * 16 + gid;
            if (rlo < NN) {
                float h0 = g_h[(size_t)rlo * 64 + gc]     + fmaxf(c[mt][nt][0] + b0, 0.f);
                float h1 = g_h[(size_t)rlo * 64 + gc + 1] + fmaxf(c[mt][nt][1] + b1, 0.f);
                g_h[(size_t)rlo * 64 + gc]     = h0;
                g_h[(size_t)rlo * 64 + gc + 1] = h1;
                s0 += h0; q0 += h0 * h0;
                s1 += h1; q1 += h1 * h1;
            }
            if (rlo + 8 < NN) {
                float h0 = g_h[(size_t)(rlo + 8) * 64 + gc]     + fmaxf(c[mt][nt][2] + b0, 0.f);
                float h1 = g_h[(size_t)(rlo + 8) * 64 + gc + 1] + fmaxf(c[mt][nt][3] + b1, 0.f);
                g_h[(size_t)(rlo + 8) * 64 + gc]     = h0;
                g_h[(size_t)(rlo + 8) * 64 + gc + 1] = h1;
                s0 += h0; q0 += h0 * h0;
                s1 += h1; q1 += h1 * h1;
            }
        }
#pragma unroll
        for (int o = 4; o < 32; o <<= 1) {
            s0 += __shfl_xor_sync(0xFFFFFFFFu, s0, o);
            s1 += __shfl_xor_sync(0xFFFFFFFFu, s1, o);
            q0 += __shfl_xor_sync(0xFFFFFFFFu, q0, o);
            q1 += __shfl_xor_sync(0xFFFFFFFFu, q1, o);
        }
        if (gid == 0) {
            atomicAdd(&g_sum[gc],      s0);
            atomicAdd(&g_sum[gc + 1],  s1);
            atomicAdd(&g_sum2[gc],     q0);
            atomicAdd(&g_sum2[gc + 1], q1);
        }
    }
}

// ---------------- fused softmax + GAT aggregate + conv + APPNP init: warp per node ----------------
__global__ __launch_bounds__(256) void msg_fused_k(
    const float* __restrict__ conv_w, const float* __restrict__ conv_b)
{
    int w = (blockIdx.x * blockDim.x + threadIdx.x) >> 5;
    int lane = threadIdx.x & 31;
    if (w >= NN) return;
    int r0 = w * ROWCAP, r1 = g_cur[w];
    const int hl = lane >> 3;
    const float er_s = g_er[w * 4 + hl];
    const uint4* __restrict__ fh4 = reinterpret_cast<const uint4*>(g_feat_h);
    unsigned long long accp[4] = {0ull, 0ull, 0ull, 0ull};
    float dsum = 0.f;

    for (int base = r0; base < r1; base += 32) {
        int nb = min(32, r1 - base);
        int idx = (base + lane < r1) ? g_csrc[base + lane] : 0;
        int j = 0;
        for (; j + 1 < nb; j += 2) {
            int s0 = __shfl_sync(0xFFFFFFFFu, idx, j);
            int s1 = __shfl_sync(0xFFFFFFFFu, idx, j + 1);
            float x0 = g_el[s0 * 4 + hl] + er_s;
            float x1 = g_el[s1 * 4 + hl] + er_s;
            uint4 f0 = fh4[(size_t)s0 * 32 + lane];
            uint4 f1 = fh4[(size_t)s1 * 32 + lane];
            x0 = (x0 > 0.f) ? x0 : NEG_SLOPE * x0;
            x1 = (x1 > 0.f) ? x1 : NEG_SLOPE * x1;
            float w0 = __expf(x0), w1 = __expf(x1);
            dsum += w0 + w1;
            unsigned long long wp0, wp1;
            asm("mov.b64 %0, {%1, %1};" : "=l"(wp0) : "f"(w0));
            asm("mov.b64 %0, {%1, %1};" : "=l"(wp1) : "f"(w1));
            const __half2* p0 = reinterpret_cast<const __half2*>(&f0);
            const __half2* p1 = reinterpret_cast<const __half2*>(&f1);
#pragma unroll
            for (int i = 0; i < 4; i++) {
                float2 t0 = __half22float2(p0[i]);
                float2 t1 = __half22float2(p1[i]);
                unsigned long long tp0, tp1;
                asm("mov.b64 %0, {%1, %2};" : "=l"(tp0) : "f"(t0.x), "f"(t0.y));
                asm("mov.b64 %0, {%1, %2};" : "=l"(tp1) : "f"(t1.x), "f"(t1.y));
                asm("fma.rn.f32x2 %0, %1, %2, %0;" : "+l"(accp[i]) : "l"(wp0), "l"(tp0));
                asm("fma.rn.f32x2 %0, %1, %2, %0;" : "+l"(accp[i]) : "l"(wp1), "l"(tp1));
            }
        }
        if (j < nb) {
            int s0 = __shfl_sync(0xFFFFFFFFu, idx, j);
            float x0 = g_el[s0 * 4 + hl] + er_s;
            uint4 f0 = fh4[(size_t)s0 * 32 + lane];
            x0 = (x0 > 0.f) ? x0 : NEG_SLOPE * x0;
            float w0 = __expf(x0);
            dsum += w0;
            unsigned long long wp0;
            asm("mov.b64 %0, {%1, %1};" : "=l"(wp0) : "f"(w0));
            const __half2* p0 = reinterpret_cast<const __half2*>(&f0);
#pragma unroll
            for (int i = 0; i < 4; i++) {
                float2 t0 = __half22float2(p0[i]);
                unsigned long long tp0;
                asm("mov.b64 %0, {%1, %2};" : "=l"(tp0) : "f"(t0.x), "f"(t0.y));
                asm("fma.rn.f32x2 %0, %1, %2, %0;" : "+l"(accp[i]) : "l"(wp0), "l"(tp0));
            }
        }
    }

    float acc[8];
#pragma unroll
    for (int i = 0; i < 4; i++)
        asm("mov.b64 {%0, %1}, %2;" : "=f"(acc[2*i]), "=f"(acc[2*i+1]) : "l"(accp[i]));

    float rden = 1.f / fmaxf(dsum, 1e-9f);
    uint4 rvu = reinterpret_cast<const uint4*>(g_rst_h)[(size_t)w * 32 + lane];
    const __half2* rp = reinterpret_cast<const __half2*>(&rvu);
    float cwh = conv_w[hl];
    float v[8];
#pragma unroll
    for (int i = 0; i < 4; i++) {
        float2 rv = __half22float2(rp[i]);
        v[2*i]   = fmaxf(acc[2*i]   * rden + rv.x, 0.f) * cwh;
        v[2*i+1] = fmaxf(acc[2*i+1] * rden + rv.y, 0.f) * cwh;
    }
#pragma unroll
    for (int i = 0; i < 8; i++) {
        v[i] += __shfl_xor_sync(0xFFFFFFFFu, v[i], 8);
        v[i] += __shfl_xor_sync(0xFFFFFFFFu, v[i], 16);
    }
    float cb = conv_b[0];
#pragma unroll
    for (int i = 0; i < 8; i++) v[i] += cb;
    float nm = rsqrtf(fmaxf((float)(r1 - r0), 1.f));
    int q = lane & 7;
    if (lane == 0) g_norm[w] = nm;
    if (lane < 8) {
        float4 a = make_float4(v[0], v[1], v[2], v[3]);
        float4 b = make_float4(v[4], v[5], v[6], v[7]);
        reinterpret_cast<float4*>(g_h0)[(size_t)w * 16 + q * 2]     = a;
        reinterpret_cast<float4*>(g_h0)[(size_t)w * 16 + q * 2 + 1] = b;
    } else if (lane < 16) {
        __half2 hx[4];
#pragma unroll
        for (int i = 0; i < 4; i++)
            hx[i] = __floats2half2_rn(v[2*i] * nm, v[2*i+1] * nm);
        reinterpret_cast<uint4*>(g_xh)[(size_t)w * 8 + q] =
            *reinterpret_cast<uint4*>(hx);
    }
}

// ---------------- fused APPNP propagate+combine: warp per node, half-warp per edge (R15 version) ----------------
__global__ __launch_bounds__(256) void prop_k(int it) {
    int w = (blockIdx.x * blockDim.x + threadIdx.x) >> 5;
    int lane = threadIdx.x & 31;
    if (w >= NN) return;
    const int half = lane >> 4, sub = lane & 15;
    const uint2* __restrict__ xin2 =
        reinterpret_cast<const uint2*>((it & 1) ? g_xh2 : g_xh);   // row = 16 uint2
    int r0 = w * ROWCAP, r1 = g_cur[w];
    float a0 = 0.f, a1 = 0.f, a2 = 0.f, a3 = 0.f;

    for (int base = r0; base < r1; base += 32) {
        int nb = min(32, r1 - base);
        int idx = (base + lane < r1) ? g_csrc[base + lane] : 0;
        int j = 0;
        for (; j + 7 < nb; j += 8) {
            int s[4];
#pragma unroll
            for (int p = 0; p < 4; p++)
                s[p] = __shfl_sync(0xFFFFFFFFu, idx, j + 2 * p + half);
            uint2 u[4];
#pragma unroll
            for (int p = 0; p < 4; p++)
                u[p] = xin2[(size_t)s[p] * 16 + sub];
#pragma unroll
            for (int p = 0; p < 4; p++) {
                float2 fa = __half22float2(*reinterpret_cast<__half2*>(&u[p].x));
                float2 fb = __half22float2(*reinterpret_cast<__half2*>(&u[p].y));
                a0 += fa.x; a1 += fa.y; a2 += fb.x; a3 += fb.y;
            }
        }
        for (; j + 1 < nb; j += 2) {
            int s0 = __shfl_sync(0xFFFFFFFFu, idx, j + half);
            uint2 u0 = xin2[(size_t)s0 * 16 + sub];
            float2 fa = __half22float2(*reinterpret_cast<__half2*>(&u0.x));
            float2 fb = __half22float2(*reinterpret_cast<__half2*>(&u0.y));
            a0 += fa.x; a1 += fa.y; a2 += fb.x; a3 += fb.y;
        }
        if (j < nb) {
            int s0 = __shfl_sync(0xFFFFFFFFu, idx, j);
            if (half == 0) {
                uint2 u0 = xin2[(size_t)s0 * 16 + sub];
                float2 fa = __half22float2(*reinterpret_cast<__half2*>(&u0.x));
                float2 fb = __half22float2(*reinterpret_cast<__half2*>(&u0.y));
                a0 += fa.x; a1 += fa.y; a2 += fb.x; a3 += fb.y;
            }
        }
    }
    a0 += __shfl_xor_sync(0xFFFFFFFFu, a0, 16);
    a1 += __shfl_xor_sync(0xFFFFFFFFu, a1, 16);
    a2 += __shfl_xor_sync(0xFFFFFFFFu, a2, 16);
    a3 += __shfl_xor_sync(0xFFFFFFFFu, a3, 16);

    if (half == 0) {
        float nm = g_norm[w];
        float4 h0 = reinterpret_cast<const float4*>(g_h0)[(size_t)w * 16 + sub];
        float t0 = 0.5f * a0 * nm + 0.5f * h0.x;
        float t1 = 0.5f * a1 * nm + 0.5f * h0.y;
        float t2 = 0.5f * a2 * nm + 0.5f * h0.z;
        float t3 = 0.5f * a3 * nm + 0.5f * h0.w;
        if (it == 4) {
            reinterpret_cast<float4*>(g_h)[(size_t)w * 16 + sub] =
                make_float4(t0, t1, t2, t3);
        } else {
            __half2 hx[2];
            hx[0] = __floats2half2_rn(t0 * nm, t1 * nm);
            hx[1] = __floats2half2_rn(t2 * nm, t3 * nm);
            uint2* xout = reinterpret_cast<uint2*>((it & 1) ? g_xh : g_xh2);
            xout[(size_t)w * 16 + sub] = *reinterpret_cast<uint2*>(hx);
        }
    }
}

// ---------------- BatchNorm finalize + output ----------------
__global__ void bnfin_k() {
    int c = threadIdx.x;
    if (c >= DD) return;
    double mu = (double)g_sum[c] / NN;
    double var = (double)g_sum2[c] / NN - mu * mu;
    g_mu[c]   = (float)mu;
    g_rstd[c] = (float)(1.0 / sqrt(var + 1e-5));
}

__global__ __launch_bounds__(256) void bnout_k(
    const float* __restrict__ gamma, const float* __restrict__ beta,
    float* __restrict__ out)
{
    int i = blockIdx.x * blockDim.x + threadIdx.x;
    if (i >= NN * DD) return;
    int c = i & 63;
    out[i] = (g_h[i] - g_mu[c]) * g_rstd[c] * gamma[c] + beta[c];
}

// ---------------- launch ----------------
extern "C" void kernel_launch(void* const* d_in, const int* in_sizes, int n_in,
                              void* d_out, int out_size) {
    const float* node      = (const float*)d_in[0];
    const int*   src       = (const int*)  d_in[1];
    const int*   dst       = (const int*)  d_in[2];
    const float* W_fc      = (const float*)d_in[3];
    const float* attn_l    = (const float*)d_in[4];
    const float* attn_r    = (const float*)d_in[5];
    const float* W_res_gat = (const float*)d_in[6];
    const float* gat_bias  = (const float*)d_in[7];
    const float* conv_w    = (const float*)d_in[8];
    const float* conv_b    = (const float*)d_in[9];
    const float* W_res     = (const float*)d_in[10];
    const float* b_res     = (const float*)d_in[11];
    const float* gamma     = (const float*)d_in[12];
    const float* beta      = (const float*)d_in[13];
    float* out = (float*)d_out;

    cvt_k<<<(NN*16 + 255)/256, 256>>>(node, W_fc, W_res_gat, W_res);

    dim3 gg(GEMM_BX, 5);
    gemm_mma_k<<<gg, 256>>>(attn_l, attn_r, gat_bias, src, dst);

    msg_fused_k<<<(NN*32 + 255)/256, 256>>>(conv_w, conv_b);

    for (int it = 0; it < 5; it++)
        prop_k<<<(NN*32 + 255)/256, 256>>>(it);

    gemm_res_k<<<(NN + 63)/64, 128>>>(b_res);

    bnfin_k<<<1, 64>>>();
    bnout_k<<<(NN*DD + 255)/256, 256>>>(gamma, beta, out);
}